// round 4
// baseline (speedup 1.0000x reference)
#include <cuda_runtime.h>
#include <math.h>

#define N_MET   100000
#define N_RXN   200000
#define E_SUB   400000
#define E_PROD  400000
#define HIDDEN  128
#define MSG     64
#define DT      0.01f

#define SCAN_BS 512
#define NB1     ((N_RXN + SCAN_BS - 1) / SCAN_BS)   // 391

#define LDT 132     // smem stride (floats) for T tile, conflict-free A-frag loads
#define LDM 136     // smem stride (floats) for M tile, conflict-free B-frag loads
#define K2_TILE 64
#define K2_NBLK (N_RXN / K2_TILE)                   // 3125, exact
#define MAXE    256 // edge-staging chunk

// smem floats: UWB(512)+c1(128)+V2(128)+bb(128)+cnt(64)+ext(64)+E(3*256)+T(64*LDT)+M(128*LDM)
#define K2_SMEM_FLOATS (512 + 128 + 128 + 128 + 64 + 64 + 3 * MAXE + K2_TILE * LDT + HIDDEN * LDM)
#define K2_SMEM_BYTES  (K2_SMEM_FLOATS * 4)

// ---------------- scratch (device globals; no allocation allowed) -------------
__device__ int      g_cnt[N_RXN];
__device__ int      g_roff[N_RXN];
__device__ int      g_part[NB1];
__device__ int      g_partx[NB1];
__device__ int      g_start[N_RXN];
__device__ int      g_cursor[N_RXN];
__device__ int      g_eidx[E_SUB];
__device__ unsigned g_Mtf[HIDDEN * HIDDEN];  // tf32 bits of W2@V1
__device__ float    g_bb[HIDDEN];            // b2 @ V1
__device__ float    g_v[N_RXN];
__device__ float    g_rscale[N_RXN];
__device__ float    g_totcons[N_MET];

__device__ __forceinline__ float tanh_fast(float x) {
    float y; asm("tanh.approx.f32 %0, %1;" : "=f"(y) : "f"(x)); return y;
}
__device__ __forceinline__ unsigned cvt_tf32(float f) {
    unsigned u; asm("cvt.rna.tf32.f32 %0, %1;" : "=r"(u) : "f"(f)); return u;
}

// ---------------- K0: init + weight folding (one launch) ----------------------
// blocks 0..127: row j of M = W2@V1 (stored as tf32 bits)
// block 128:     bb = b2@V1
// blocks 129+ :  zero g_cnt, g_totcons, out
__global__ void k_init(const float* __restrict__ W2,
                       const float* __restrict__ V1,
                       const float* __restrict__ b2,
                       float* __restrict__ out)
{
    int blk = blockIdx.x, tid = threadIdx.x;
    if (blk < HIDDEN) {
        float acc = 0.f;
        for (int k = 0; k < MSG; k++)
            acc = fmaf(W2[blk * MSG + k], V1[k * HIDDEN + tid], acc);
        g_Mtf[blk * HIDDEN + tid] = cvt_tf32(acc);
    } else if (blk == HIDDEN) {
        float acc = 0.f;
        for (int k = 0; k < MSG; k++)
            acc = fmaf(b2[k], V1[k * HIDDEN + tid], acc);
        g_bb[tid] = acc;
    } else {
        int i = (blk - 129) * blockDim.x + tid;
        int stride = (gridDim.x - 129) * blockDim.x;
        for (int p = i; p < N_RXN; p += stride) g_cnt[p] = 0;
        for (int p = i; p < N_MET; p += stride) { g_totcons[p] = 0.f; out[p] = 0.f; }
    }
}

// ---------------- CSR build ---------------------------------------------------
__global__ void k_hist(const int* __restrict__ rxn_sub) {
    int e = blockIdx.x * blockDim.x + threadIdx.x;
    if (e < E_SUB) atomicAdd(&g_cnt[rxn_sub[e]], 1);
}

__global__ void k_scan1() {
    __shared__ int s[SCAN_BS];
    int b = blockIdx.x, t = threadIdx.x;
    int i = b * SCAN_BS + t;
    int v = (i < N_RXN) ? g_cnt[i] : 0;
    s[t] = v; __syncthreads();
    for (int off = 1; off < SCAN_BS; off <<= 1) {
        int x = (t >= off) ? s[t - off] : 0;
        __syncthreads();
        s[t] += x;
        __syncthreads();
    }
    if (i < N_RXN) g_roff[i] = s[t] - v;
    if (t == SCAN_BS - 1) g_part[b] = s[t];
}

__global__ void k_scan2() {
    __shared__ int s[SCAN_BS];
    int t = threadIdx.x;
    int v = (t < NB1) ? g_part[t] : 0;
    s[t] = v; __syncthreads();
    for (int off = 1; off < SCAN_BS; off <<= 1) {
        int x = (t >= off) ? s[t - off] : 0;
        __syncthreads();
        s[t] += x;
        __syncthreads();
    }
    if (t < NB1) g_partx[t] = s[t] - v;
}

__global__ void k_start() {
    int r = blockIdx.x * blockDim.x + threadIdx.x;
    if (r >= N_RXN) return;
    int st = g_roff[r] + g_partx[r >> 9];
    g_start[r]  = st;
    g_cursor[r] = st;
}

__global__ void k_scatter(const int* __restrict__ rxn_sub) {
    int e = blockIdx.x * blockDim.x + threadIdx.x;
    if (e >= E_SUB) return;
    int pos = atomicAdd(&g_cursor[rxn_sub[e]], 1);
    g_eidx[pos] = e;
}

// ---------------- K2: staged gather + layer1 + tf32 GEMM + epilogue -----------
__global__ __launch_bounds__(128)
void k2_gemm(const float* __restrict__ x,
             const int*   __restrict__ met_sub,
             const float* __restrict__ sto_sub,
             const float* __restrict__ W1,
             const float* __restrict__ b1,
             const float* __restrict__ c1v,
             const float* __restrict__ V2,
             const float* __restrict__ c2,
             const float* __restrict__ log_k)
{
    extern __shared__ float sm[];
    float4*   sUWB = (float4*)sm;                      // 128 x {U,W,B,pad}
    float*    sc1  = sm + 512;
    float*    sV2  = sc1 + 128;
    float*    sbb  = sV2 + 128;
    float*    scnt = sbb + 128;                        // 64
    float*    sext = scnt + 64;                        // 64
    float*    sEa  = sext + 64;                        // MAXE
    float*    sEe  = sEa + MAXE;                       // MAXE
    float*    sEs  = sEe + MAXE;                       // MAXE
    float*    sT   = sEs + MAXE;                       // 64*LDT (tf32 bits)
    unsigned* sM   = (unsigned*)(sT + K2_TILE * LDT);  // 128*LDM tf32 bits

    int tid = threadIdx.x, blk = blockIdx.x;

    // stage weights & biases
    sUWB[tid] = make_float4(W1[tid], W1[HIDDEN + tid], b1[tid], 0.f);
    sc1[tid]  = c1v[tid];
    sV2[tid]  = V2[tid];
    sbb[tid]  = g_bb[tid];
    for (int i = tid; i < HIDDEN * HIDDEN; i += 128) {
        int rw = i >> 7, cl = i & 127;
        sM[rw * LDM + cl] = g_Mtf[i];
    }

    // block edge range (contiguous in CSR order)
    int r_first = blk * K2_TILE;
    int e_begin = g_start[r_first];
    int last    = r_first + K2_TILE - 1;
    int totE    = g_start[last] + g_cnt[last] - e_begin;

    int row = tid >> 1, half = tid & 1, j0 = half * 64;
    int r     = r_first + row;
    int s_rel = g_start[r] - e_begin;
    int c     = g_cnt[r];

    float acc[64];
    #pragma unroll
    for (int j = 0; j < 64; j++) acc[j] = 0.f;
    float exts = 0.f;

    for (int base = 0; base < totE; base += MAXE) {
        int ch = min(MAXE, totE - base);
        __syncthreads();   // protect smem reuse across chunks (also covers first staging)
        for (int i = tid; i < ch; i += 128) {
            int idx = g_eidx[e_begin + base + i];
            int met = met_sub[idx];
            sEa[i] = x[met * 8 + 3];
            sEe[i] = x[met * 8 + 4];
            sEs[i] = sto_sub[idx];
        }
        __syncthreads();
        int lo = max(s_rel, base), hi = min(s_rel + c, base + ch);
        for (int l = lo; l < hi; l++) {
            float a   = sEa[l - base];
            float sto = sEs[l - base];
            if (half == 0) exts += sEe[l - base];
            #pragma unroll
            for (int j = 0; j < 64; j++) {
                float4 uwb = sUWB[j0 + j];
                acc[j] += tanh_fast(fmaf(a, uwb.x, fmaf(sto, uwb.y, uwb.z)));
            }
        }
    }

    #pragma unroll
    for (int j = 0; j < 64; j++)
        sT[row * LDT + j0 + j] = __uint_as_float(cvt_tf32(acc[j]));
    if (half == 0) { scnt[row] = (float)c; sext[row] = exts; }
    __syncthreads();

    // ---- mma phase: 4 warps x 16 rows each ----
    int w = tid >> 5, lane = tid & 31, gid = lane >> 2, tig = lane & 3;

    unsigned afr[16][4];
    #pragma unroll
    for (int kt = 0; kt < 16; kt++) {
        int k = kt * 8;
        afr[kt][0] = __float_as_uint(sT[(w * 16 + gid)     * LDT + k + tig]);
        afr[kt][1] = __float_as_uint(sT[(w * 16 + gid + 8) * LDT + k + tig]);
        afr[kt][2] = __float_as_uint(sT[(w * 16 + gid)     * LDT + k + 4 + tig]);
        afr[kt][3] = __float_as_uint(sT[(w * 16 + gid + 8) * LDT + k + 4 + tig]);
    }
    float cnt0 = scnt[w * 16 + gid], cnt1 = scnt[w * 16 + gid + 8];
    float acc0 = 0.f, acc1 = 0.f;

    for (int nt = 0; nt < 16; nt++) {
        float c0 = 0.f, c1f = 0.f, c2f = 0.f, c3f = 0.f;
        int n0 = nt * 8;
        #pragma unroll
        for (int kt = 0; kt < 16; kt++) {
            unsigned b0  = sM[(kt * 8 + tig)     * LDM + n0 + gid];
            unsigned b1r = sM[(kt * 8 + tig + 4) * LDM + n0 + gid];
            asm volatile(
                "mma.sync.aligned.m16n8k8.row.col.f32.tf32.tf32.f32 "
                "{%0,%1,%2,%3}, {%4,%5,%6,%7}, {%8,%9}, {%0,%1,%2,%3};"
                : "+f"(c0), "+f"(c1f), "+f"(c2f), "+f"(c3f)
                : "r"(afr[kt][0]), "r"(afr[kt][1]), "r"(afr[kt][2]), "r"(afr[kt][3]),
                  "r"(b0), "r"(b1r));
        }
        int col0 = n0 + 2 * tig, col1 = col0 + 1;
        float bi0 = sc1[col0], bi1 = sc1[col1];
        float bb0 = sbb[col0], bb1 = sbb[col1];
        float v0  = sV2[col0], v1  = sV2[col1];
        acc0 += tanh_fast(fmaf(cnt0, bb0, c0)  + bi0) * v0
              + tanh_fast(fmaf(cnt0, bb1, c1f) + bi1) * v1;
        acc1 += tanh_fast(fmaf(cnt1, bb0, c2f) + bi0) * v0
              + tanh_fast(fmaf(cnt1, bb1, c3f) + bi1) * v1;
    }

    acc0 += __shfl_xor_sync(0xffffffffu, acc0, 1);
    acc0 += __shfl_xor_sync(0xffffffffu, acc0, 2);
    acc1 += __shfl_xor_sync(0xffffffffu, acc1, 1);
    acc1 += __shfl_xor_sync(0xffffffffu, acc1, 2);

    if (tig == 0) {
        float c2s = c2[0];
        int r0 = r_first + w * 16 + gid;
        {
            float z    = acc0 + c2s;
            float base = fmaxf(z, 0.f) + log1pf(expf(-fabsf(z)));
            float extm = sext[w * 16 + gid] / fmaxf(scnt[w * 16 + gid], 1.f);
            g_v[r0]      = exp10f(log_k[r0]) * extm * base;
            g_rscale[r0] = 1.f;
        }
        int r1 = r0 + 8;
        {
            float z    = acc1 + c2s;
            float base = fmaxf(z, 0.f) + log1pf(expf(-fabsf(z)));
            float extm = sext[w * 16 + gid + 8] / fmaxf(scnt[w * 16 + gid + 8], 1.f);
            g_v[r1]      = exp10f(log_k[r1]) * extm * base;
            g_rscale[r1] = 1.f;
        }
    }
}

// ---------------- small scatter kernels ---------------------------------------
__global__ void k_totcons(const int* __restrict__ met_sub,
                          const int* __restrict__ rxn_sub,
                          const float* __restrict__ sto_sub)
{
    int e = blockIdx.x * blockDim.x + threadIdx.x;
    if (e >= E_SUB) return;
    float c = sto_sub[e] * g_v[rxn_sub[e]] * DT;
    atomicAdd(&g_totcons[met_sub[e]], c);
}

__global__ void k_rscale(const float* __restrict__ x,
                         const int* __restrict__ met_sub,
                         const int* __restrict__ rxn_sub)
{
    int e = blockIdx.x * blockDim.x + threadIdx.x;
    if (e >= E_SUB) return;
    int   m    = met_sub[e];
    float tot  = g_totcons[m];
    float conc = x[m * 8 + 3];
    float sc   = (tot > 1e-12f) ? fminf(conc / tot, 1.0f) : 1.0f;
    atomicMin(reinterpret_cast<int*>(&g_rscale[rxn_sub[e]]), __float_as_int(sc));
}

__global__ void k_contrib(const int* __restrict__ met_sub,
                          const int* __restrict__ rxn_sub,
                          const float* __restrict__ sto_sub,
                          const int* __restrict__ met_prod,
                          const int* __restrict__ rxn_prod,
                          const float* __restrict__ sto_prod,
                          float* __restrict__ out)
{
    int i = blockIdx.x * blockDim.x + threadIdx.x;
    if (i >= E_SUB + E_PROD) return;
    int m, r; float sto;
    if (i < E_SUB) {
        m = met_sub[i];  r = rxn_sub[i];  sto = -sto_sub[i];
    } else {
        int e = i - E_SUB;
        m = met_prod[e]; r = rxn_prod[e]; sto = sto_prod[e];
    }
    atomicAdd(&out[m], sto * g_v[r] * g_rscale[r]);
}

// ---------------- launch ------------------------------------------------------
extern "C" void kernel_launch(void* const* d_in, const int* in_sizes, int n_in,
                              void* d_out, int out_size)
{
    const float* x        = (const float*)d_in[0];
    const int*   met_sub  = (const int*)  d_in[1];
    const int*   rxn_sub  = (const int*)  d_in[2];
    const float* sto_sub  = (const float*)d_in[3];
    const int*   met_prod = (const int*)  d_in[4];
    const int*   rxn_prod = (const int*)  d_in[5];
    const float* sto_prod = (const float*)d_in[6];
    const float* W1       = (const float*)d_in[7];
    const float* b1       = (const float*)d_in[8];
    const float* W2       = (const float*)d_in[9];
    const float* b2       = (const float*)d_in[10];
    const float* V1       = (const float*)d_in[11];
    const float* c1       = (const float*)d_in[12];
    const float* V2       = (const float*)d_in[13];
    const float* c2       = (const float*)d_in[14];
    const float* log_k    = (const float*)d_in[15];
    float* out = (float*)d_out;

    cudaFuncSetAttribute(k2_gemm, cudaFuncAttributeMaxDynamicSharedMemorySize,
                         K2_SMEM_BYTES);

    k_init<<<129 + 1024, 128>>>(W2, V1, b2, out);

    k_hist<<<(E_SUB + 255) / 256, 256>>>(rxn_sub);
    k_scan1<<<NB1, SCAN_BS>>>();
    k_scan2<<<1, SCAN_BS>>>();
    k_start<<<(N_RXN + 255) / 256, 256>>>();
    k_scatter<<<(E_SUB + 255) / 256, 256>>>(rxn_sub);

    k2_gemm<<<K2_NBLK, 128, K2_SMEM_BYTES>>>(x, met_sub, sto_sub,
                                             W1, b1, c1, V2, c2, log_k);

    k_totcons<<<(E_SUB + 255) / 256, 256>>>(met_sub, rxn_sub, sto_sub);
    k_rscale<<<(E_SUB + 255) / 256, 256>>>(x, met_sub, rxn_sub);
    k_contrib<<<(E_SUB + E_PROD + 255) / 256, 256>>>(
        met_sub, rxn_sub, sto_sub, met_prod, rxn_prod, sto_prod, out);
}

// round 5
// speedup vs baseline: 4.1109x; 4.1109x over previous
#include <cuda_runtime.h>
#include <math.h>

#define N_MET   100000
#define N_RXN   200000
#define E_SUB   400000
#define E_PROD  400000
#define HIDDEN  128
#define MSG     64
#define DT      0.01f

#define SCAN_BS 512
#define NB1     ((N_RXN + SCAN_BS - 1) / SCAN_BS)   // 391

#define LDT 132     // smem stride (floats) for T tile
#define LDM 136     // smem stride (floats) for M tile
#define K2_TILE 64
#define K2_NBLK (N_RXN / K2_TILE)                   // 3125, exact
#define MAXE    256 // edge-staging chunk

// smem floats: UWB(512)+c1(128)+V2(128)+bb(128)+cnt(64)+ext(64)+E(3*256)+T(64*LDT)+M(128*LDM)
#define K2_SMEM_FLOATS (512 + 128 + 128 + 128 + 64 + 64 + 3 * MAXE + K2_TILE * LDT + HIDDEN * LDM)
#define K2_SMEM_BYTES  (K2_SMEM_FLOATS * 4)

// ---------------- scratch (device globals; no allocation allowed) -------------
__device__ int      g_cnt[N_RXN];
__device__ int      g_roff[N_RXN];
__device__ int      g_part[NB1];
__device__ int      g_partx[NB1];
__device__ int      g_start[N_RXN];
__device__ int      g_cursor[N_RXN];
__device__ int      g_eidx[E_SUB];
__device__ unsigned g_Mtf[HIDDEN * HIDDEN];  // tf32 bits of W2@V1
__device__ float    g_bb[HIDDEN];            // b2 @ V1
__device__ float    g_v[N_RXN];
__device__ float    g_rscale[N_RXN];
__device__ float    g_totcons[N_MET];

__device__ __forceinline__ float tanh_fast(float x) {
    float y; asm("tanh.approx.f32 %0, %1;" : "=f"(y) : "f"(x)); return y;
}
__device__ __forceinline__ unsigned cvt_tf32(float f) {
    unsigned u; asm("cvt.rna.tf32.f32 %0, %1;" : "=r"(u) : "f"(f)); return u;
}

// ---------------- K0: init + weight folding (one launch) ----------------------
__global__ void k_init(const float* __restrict__ W2,
                       const float* __restrict__ V1,
                       const float* __restrict__ b2,
                       float* __restrict__ out)
{
    int blk = blockIdx.x, tid = threadIdx.x;
    if (blk < HIDDEN) {
        float acc = 0.f;
        for (int k = 0; k < MSG; k++)
            acc = fmaf(W2[blk * MSG + k], V1[k * HIDDEN + tid], acc);
        g_Mtf[blk * HIDDEN + tid] = cvt_tf32(acc);
    } else if (blk == HIDDEN) {
        float acc = 0.f;
        for (int k = 0; k < MSG; k++)
            acc = fmaf(b2[k], V1[k * HIDDEN + tid], acc);
        g_bb[tid] = acc;
    } else {
        int i = (blk - 129) * blockDim.x + tid;
        int stride = (gridDim.x - 129) * blockDim.x;
        for (int p = i; p < N_RXN; p += stride) g_cnt[p] = 0;
        for (int p = i; p < N_MET; p += stride) { g_totcons[p] = 0.f; out[p] = 0.f; }
    }
}

// ---------------- CSR build ---------------------------------------------------
__global__ void k_hist(const int* __restrict__ rxn_sub) {
    int e = blockIdx.x * blockDim.x + threadIdx.x;
    if (e < E_SUB) atomicAdd(&g_cnt[rxn_sub[e]], 1);
}

__global__ void k_scan1() {
    __shared__ int s[SCAN_BS];
    int b = blockIdx.x, t = threadIdx.x;
    int i = b * SCAN_BS + t;
    int v = (i < N_RXN) ? g_cnt[i] : 0;
    s[t] = v; __syncthreads();
    for (int off = 1; off < SCAN_BS; off <<= 1) {
        int x = (t >= off) ? s[t - off] : 0;
        __syncthreads();
        s[t] += x;
        __syncthreads();
    }
    if (i < N_RXN) g_roff[i] = s[t] - v;
    if (t == SCAN_BS - 1) g_part[b] = s[t];
}

__global__ void k_scan2() {
    __shared__ int s[SCAN_BS];
    int t = threadIdx.x;
    int v = (t < NB1) ? g_part[t] : 0;
    s[t] = v; __syncthreads();
    for (int off = 1; off < SCAN_BS; off <<= 1) {
        int x = (t >= off) ? s[t - off] : 0;
        __syncthreads();
        s[t] += x;
        __syncthreads();
    }
    if (t < NB1) g_partx[t] = s[t] - v;
}

__global__ void k_start() {
    int r = blockIdx.x * blockDim.x + threadIdx.x;
    if (r >= N_RXN) return;
    int st = g_roff[r] + g_partx[r >> 9];
    g_start[r]  = st;
    g_cursor[r] = st;
}

__global__ void k_scatter(const int* __restrict__ rxn_sub) {
    int e = blockIdx.x * blockDim.x + threadIdx.x;
    if (e >= E_SUB) return;
    int pos = atomicAdd(&g_cursor[rxn_sub[e]], 1);
    g_eidx[pos] = e;
}

// ---------------- K2: staged gather + layer1 + tf32 GEMM + epilogue -----------
// 256 threads: layer-1 = 64 rows x 4 threads (32 units each, stride-4 mapping).
// MMA phase on warps 0-3 only.
__global__ __launch_bounds__(256)
void k2_gemm(const float* __restrict__ x,
             const int*   __restrict__ met_sub,
             const float* __restrict__ sto_sub,
             const float* __restrict__ W1,
             const float* __restrict__ b1,
             const float* __restrict__ c1v,
             const float* __restrict__ V2,
             const float* __restrict__ c2,
             const float* __restrict__ log_k)
{
    extern __shared__ float sm[];
    float4*   sUWB = (float4*)sm;                      // 128 x {U,W,B,pad}
    float*    sc1  = sm + 512;
    float*    sV2  = sc1 + 128;
    float*    sbb  = sV2 + 128;
    float*    scnt = sbb + 128;                        // 64
    float*    sext = scnt + 64;                        // 64
    float*    sEa  = sext + 64;                        // MAXE
    float*    sEe  = sEa + MAXE;                       // MAXE
    float*    sEs  = sEe + MAXE;                       // MAXE
    float*    sT   = sEs + MAXE;                       // 64*LDT (tf32 bits)
    unsigned* sM   = (unsigned*)(sT + K2_TILE * LDT);  // 128*LDM tf32 bits

    int tid = threadIdx.x, blk = blockIdx.x;

    // stage weights & biases (256 threads)
    if (tid < 128) {
        sUWB[tid] = make_float4(W1[tid], W1[HIDDEN + tid], b1[tid], 0.f);
        sc1[tid]  = c1v[tid];
        sV2[tid]  = V2[tid];
        sbb[tid]  = g_bb[tid];
    }
    for (int i = tid; i < HIDDEN * HIDDEN; i += 256) {
        int rw = i >> 7, cl = i & 127;
        sM[rw * LDM + cl] = g_Mtf[i];
    }

    // block edge range (contiguous in CSR order)
    int r_first = blk * K2_TILE;
    int e_begin = g_start[r_first];
    int last    = r_first + K2_TILE - 1;
    int totE    = g_start[last] + g_cnt[last] - e_begin;

    int row = tid >> 2, q = tid & 3;   // 64 rows x 4 sub-threads
    int r     = r_first + row;
    int s_rel = g_start[r] - e_begin;
    int c     = g_cnt[r];

    float acc[32];
    #pragma unroll
    for (int i = 0; i < 32; i++) acc[i] = 0.f;
    float exts = 0.f;

    for (int base = 0; base < totE; base += MAXE) {
        int ch = min(MAXE, totE - base);
        __syncthreads();   // smem reuse boundary (also covers initial staging)
        for (int i = tid; i < ch; i += 256) {
            int idx = g_eidx[e_begin + base + i];
            int met = met_sub[idx];
            sEa[i] = x[met * 8 + 3];
            sEe[i] = x[met * 8 + 4];
            sEs[i] = sto_sub[idx];
        }
        __syncthreads();
        int lo = max(s_rel, base), hi = min(s_rel + c, base + ch);
        for (int l = lo; l < hi; l++) {
            float a   = sEa[l - base];
            float sto = sEs[l - base];
            if (q == 0) exts += sEe[l - base];
            #pragma unroll
            for (int i = 0; i < 32; i++) {
                float4 uwb = sUWB[q + 4 * i];   // stride-4: conflict-free across q
                acc[i] += tanh_fast(fmaf(a, uwb.x, fmaf(sto, uwb.y, uwb.z)));
            }
        }
    }

    #pragma unroll
    for (int i = 0; i < 32; i++)
        sT[row * LDT + q + 4 * i] = __uint_as_float(cvt_tf32(acc[i]));
    if (q == 0) { scnt[row] = (float)c; sext[row] = exts; }
    __syncthreads();

    if (tid >= 128) return;   // no barriers below; warps 4-7 done

    // ---- mma phase: 4 warps x 16 rows each ----
    int w = tid >> 5, lane = tid & 31, gid = lane >> 2, tig = lane & 3;

    unsigned afr[16][4];
    #pragma unroll
    for (int kt = 0; kt < 16; kt++) {
        int k = kt * 8;
        afr[kt][0] = __float_as_uint(sT[(w * 16 + gid)     * LDT + k + tig]);
        afr[kt][1] = __float_as_uint(sT[(w * 16 + gid + 8) * LDT + k + tig]);
        afr[kt][2] = __float_as_uint(sT[(w * 16 + gid)     * LDT + k + 4 + tig]);
        afr[kt][3] = __float_as_uint(sT[(w * 16 + gid + 8) * LDT + k + 4 + tig]);
    }
    float cnt0 = scnt[w * 16 + gid], cnt1 = scnt[w * 16 + gid + 8];
    float acc0 = 0.f, acc1 = 0.f;

    for (int nt = 0; nt < 16; nt++) {
        float c0 = 0.f, c1f = 0.f, c2f = 0.f, c3f = 0.f;
        int n0 = nt * 8;
        #pragma unroll
        for (int kt = 0; kt < 16; kt++) {
            unsigned b0  = sM[(kt * 8 + tig)     * LDM + n0 + gid];
            unsigned b1r = sM[(kt * 8 + tig + 4) * LDM + n0 + gid];
            asm volatile(
                "mma.sync.aligned.m16n8k8.row.col.f32.tf32.tf32.f32 "
                "{%0,%1,%2,%3}, {%4,%5,%6,%7}, {%8,%9}, {%0,%1,%2,%3};"
                : "+f"(c0), "+f"(c1f), "+f"(c2f), "+f"(c3f)
                : "r"(afr[kt][0]), "r"(afr[kt][1]), "r"(afr[kt][2]), "r"(afr[kt][3]),
                  "r"(b0), "r"(b1r));
        }
        int col0 = n0 + 2 * tig, col1 = col0 + 1;
        float bi0 = sc1[col0], bi1 = sc1[col1];
        float bb0 = sbb[col0], bb1 = sbb[col1];
        float v0  = sV2[col0], v1  = sV2[col1];
        acc0 += tanh_fast(fmaf(cnt0, bb0, c0)  + bi0) * v0
              + tanh_fast(fmaf(cnt0, bb1, c1f) + bi1) * v1;
        acc1 += tanh_fast(fmaf(cnt1, bb0, c2f) + bi0) * v0
              + tanh_fast(fmaf(cnt1, bb1, c3f) + bi1) * v1;
    }

    acc0 += __shfl_xor_sync(0xffffffffu, acc0, 1);
    acc0 += __shfl_xor_sync(0xffffffffu, acc0, 2);
    acc1 += __shfl_xor_sync(0xffffffffu, acc1, 1);
    acc1 += __shfl_xor_sync(0xffffffffu, acc1, 2);

    if (tig == 0) {
        float c2s = c2[0];
        int r0 = r_first + w * 16 + gid;
        {
            float z    = acc0 + c2s;
            float base = fmaxf(z, 0.f) + log1pf(expf(-fabsf(z)));
            float extm = sext[w * 16 + gid] / fmaxf(scnt[w * 16 + gid], 1.f);
            g_v[r0]      = exp10f(log_k[r0]) * extm * base;
            g_rscale[r0] = 1.f;
        }
        int r1 = r0 + 8;
        {
            float z    = acc1 + c2s;
            float base = fmaxf(z, 0.f) + log1pf(expf(-fabsf(z)));
            float extm = sext[w * 16 + gid + 8] / fmaxf(scnt[w * 16 + gid + 8], 1.f);
            g_v[r1]      = exp10f(log_k[r1]) * extm * base;
            g_rscale[r1] = 1.f;
        }
    }
}

// ---------------- small scatter kernels ---------------------------------------
__global__ void k_totcons(const int* __restrict__ met_sub,
                          const int* __restrict__ rxn_sub,
                          const float* __restrict__ sto_sub)
{
    int e = blockIdx.x * blockDim.x + threadIdx.x;
    if (e >= E_SUB) return;
    float c = sto_sub[e] * g_v[rxn_sub[e]] * DT;
    atomicAdd(&g_totcons[met_sub[e]], c);
}

__global__ void k_rscale(const float* __restrict__ x,
                         const int* __restrict__ met_sub,
                         const int* __restrict__ rxn_sub)
{
    int e = blockIdx.x * blockDim.x + threadIdx.x;
    if (e >= E_SUB) return;
    int   m    = met_sub[e];
    float tot  = g_totcons[m];
    float conc = x[m * 8 + 3];
    float sc   = (tot > 1e-12f) ? fminf(conc / tot, 1.0f) : 1.0f;
    atomicMin(reinterpret_cast<int*>(&g_rscale[rxn_sub[e]]), __float_as_int(sc));
}

__global__ void k_contrib(const int* __restrict__ met_sub,
                          const int* __restrict__ rxn_sub,
                          const float* __restrict__ sto_sub,
                          const int* __restrict__ met_prod,
                          const int* __restrict__ rxn_prod,
                          const float* __restrict__ sto_prod,
                          float* __restrict__ out)
{
    int i = blockIdx.x * blockDim.x + threadIdx.x;
    if (i >= E_SUB + E_PROD) return;
    int m, r; float sto;
    if (i < E_SUB) {
        m = met_sub[i];  r = rxn_sub[i];  sto = -sto_sub[i];
    } else {
        int e = i - E_SUB;
        m = met_prod[e]; r = rxn_prod[e]; sto = sto_prod[e];
    }
    atomicAdd(&out[m], sto * g_v[r] * g_rscale[r]);
}

// ---------------- launch ------------------------------------------------------
extern "C" void kernel_launch(void* const* d_in, const int* in_sizes, int n_in,
                              void* d_out, int out_size)
{
    const float* x        = (const float*)d_in[0];
    const int*   met_sub  = (const int*)  d_in[1];
    const int*   rxn_sub  = (const int*)  d_in[2];
    const float* sto_sub  = (const float*)d_in[3];
    const int*   met_prod = (const int*)  d_in[4];
    const int*   rxn_prod = (const int*)  d_in[5];
    const float* sto_prod = (const float*)d_in[6];
    const float* W1       = (const float*)d_in[7];
    const float* b1       = (const float*)d_in[8];
    const float* W2       = (const float*)d_in[9];
    const float* b2       = (const float*)d_in[10];
    const float* V1       = (const float*)d_in[11];
    const float* c1       = (const float*)d_in[12];
    const float* V2       = (const float*)d_in[13];
    const float* c2       = (const float*)d_in[14];
    const float* log_k    = (const float*)d_in[15];
    float* out = (float*)d_out;

    cudaFuncSetAttribute(k2_gemm, cudaFuncAttributeMaxDynamicSharedMemorySize,
                         K2_SMEM_BYTES);

    k_init<<<129 + 1024, 128>>>(W2, V1, b2, out);

    k_hist<<<(E_SUB + 255) / 256, 256>>>(rxn_sub);
    k_scan1<<<NB1, SCAN_BS>>>();
    k_scan2<<<1, SCAN_BS>>>();
    k_start<<<(N_RXN + 255) / 256, 256>>>();
    k_scatter<<<(E_SUB + 255) / 256, 256>>>(rxn_sub);

    k2_gemm<<<K2_NBLK, 256, K2_SMEM_BYTES>>>(x, met_sub, sto_sub,
                                             W1, b1, c1, V2, c2, log_k);

    k_totcons<<<(E_SUB + 255) / 256, 256>>>(met_sub, rxn_sub, sto_sub);
    k_rscale<<<(E_SUB + 255) / 256, 256>>>(x, met_sub, rxn_sub);
    k_contrib<<<(E_SUB + E_PROD + 255) / 256, 256>>>(
        met_sub, rxn_sub, sto_sub, met_prod, rxn_prod, sto_prod, out);
}

// round 6
// speedup vs baseline: 5.9024x; 1.4358x over previous
#include <cuda_runtime.h>
#include <math.h>

#define N_MET   100000
#define N_RXN   200000
#define E_SUB   400000
#define E_PROD  400000
#define HIDDEN  128
#define MSG     64
#define DT      0.01f

#define SCAN_BS 512
#define NB1     ((N_RXN + SCAN_BS - 1) / SCAN_BS)   // 391

#define LDT 132     // smem stride (floats) for T tile
#define LDM 136     // smem stride (floats) for M tile
#define K2_TILE 64
#define K2_NTILES (N_RXN / K2_TILE)                 // 3125, exact
#define K2_GRID  296                                // 2 CTAs/SM, one wave
#define MAXE    256 // edge-staging chunk

// smem floats: UWB(512)+c1(128)+V2(128)+bb(128)+cnt(64)+ext(64)+P(128)+E(3*256)+T(64*LDT)+M(128*LDM)
#define K2_SMEM_FLOATS (512 + 128 + 128 + 128 + 64 + 64 + 128 + 3 * MAXE + K2_TILE * LDT + HIDDEN * LDM)
#define K2_SMEM_BYTES  (K2_SMEM_FLOATS * 4)

// ---------------- scratch (device globals; no allocation allowed) -------------
__device__ int      g_cnt[N_RXN];
__device__ int      g_roff[N_RXN];
__device__ int      g_part[NB1];
__device__ int      g_partx[NB1];
__device__ int      g_start[N_RXN];
__device__ int      g_cursor[N_RXN];
__device__ int      g_eidx[E_SUB];
__device__ unsigned g_Mtf[HIDDEN * HIDDEN];  // tf32 bits of W2@V1
__device__ float    g_bb[HIDDEN];            // b2 @ V1
__device__ float    g_v[N_RXN];
__device__ float    g_rscale[N_RXN];
__device__ float    g_totcons[N_MET];

__device__ __forceinline__ float tanh_fast(float x) {
    float y; asm("tanh.approx.f32 %0, %1;" : "=f"(y) : "f"(x)); return y;
}
__device__ __forceinline__ unsigned cvt_tf32(float f) {
    unsigned u; asm("cvt.rna.tf32.f32 %0, %1;" : "=r"(u) : "f"(f)); return u;
}

// ---------------- K0: init + weight folding (one launch) ----------------------
__global__ void k_init(const float* __restrict__ W2,
                       const float* __restrict__ V1,
                       const float* __restrict__ b2,
                       float* __restrict__ out)
{
    int blk = blockIdx.x, tid = threadIdx.x;
    if (blk < HIDDEN) {
        float acc = 0.f;
        for (int k = 0; k < MSG; k++)
            acc = fmaf(W2[blk * MSG + k], V1[k * HIDDEN + tid], acc);
        g_Mtf[blk * HIDDEN + tid] = cvt_tf32(acc);
    } else if (blk == HIDDEN) {
        float acc = 0.f;
        for (int k = 0; k < MSG; k++)
            acc = fmaf(b2[k], V1[k * HIDDEN + tid], acc);
        g_bb[tid] = acc;
    } else {
        int i = (blk - 129) * blockDim.x + tid;
        int stride = (gridDim.x - 129) * blockDim.x;
        for (int p = i; p < N_RXN; p += stride) g_cnt[p] = 0;
        for (int p = i; p < N_MET; p += stride) { g_totcons[p] = 0.f; out[p] = 0.f; }
    }
}

// ---------------- CSR build ---------------------------------------------------
__global__ void k_hist(const int* __restrict__ rxn_sub) {
    int e = blockIdx.x * blockDim.x + threadIdx.x;
    if (e < E_SUB) atomicAdd(&g_cnt[rxn_sub[e]], 1);
}

__global__ void k_scan1() {
    __shared__ int s[SCAN_BS];
    int b = blockIdx.x, t = threadIdx.x;
    int i = b * SCAN_BS + t;
    int v = (i < N_RXN) ? g_cnt[i] : 0;
    s[t] = v; __syncthreads();
    for (int off = 1; off < SCAN_BS; off <<= 1) {
        int x = (t >= off) ? s[t - off] : 0;
        __syncthreads();
        s[t] += x;
        __syncthreads();
    }
    if (i < N_RXN) g_roff[i] = s[t] - v;
    if (t == SCAN_BS - 1) g_part[b] = s[t];
}

__global__ void k_scan2() {
    __shared__ int s[SCAN_BS];
    int t = threadIdx.x;
    int v = (t < NB1) ? g_part[t] : 0;
    s[t] = v; __syncthreads();
    for (int off = 1; off < SCAN_BS; off <<= 1) {
        int x = (t >= off) ? s[t - off] : 0;
        __syncthreads();
        s[t] += x;
        __syncthreads();
    }
    if (t < NB1) g_partx[t] = s[t] - v;
}

__global__ void k_start() {
    int r = blockIdx.x * blockDim.x + threadIdx.x;
    if (r >= N_RXN) return;
    int st = g_roff[r] + g_partx[r >> 9];
    g_start[r]  = st;
    g_cursor[r] = st;
}

__global__ void k_scatter(const int* __restrict__ rxn_sub) {
    int e = blockIdx.x * blockDim.x + threadIdx.x;
    if (e >= E_SUB) return;
    int pos = atomicAdd(&g_cursor[rxn_sub[e]], 1);
    g_eidx[pos] = e;
}

// ---------------- K2: persistent multi-tile: gather + layer1 + tf32 GEMM ------
// 256 threads. Weights staged once per block; ~11 tiles per block.
// layer-1: 64 rows x 4 threads (32 units each). mma: 8 warps (nt split 2-way).
__global__ __launch_bounds__(256)
void k2_gemm(const float* __restrict__ x,
             const int*   __restrict__ met_sub,
             const float* __restrict__ sto_sub,
             const float* __restrict__ W1,
             const float* __restrict__ b1,
             const float* __restrict__ c1v,
             const float* __restrict__ V2,
             const float* __restrict__ c2,
             const float* __restrict__ log_k)
{
    extern __shared__ float sm[];
    float4*   sUWB = (float4*)sm;                      // 128 x {U,W,B,pad}
    float*    sc1  = sm + 512;
    float*    sV2  = sc1 + 128;
    float*    sbb  = sV2 + 128;
    float*    scnt = sbb + 128;                        // 64
    float*    sext = scnt + 64;                        // 64
    float*    sP   = sext + 64;                        // 128 (cross-warp partials)
    float*    sEa  = sP + 128;                         // MAXE
    float*    sEe  = sEa + MAXE;                       // MAXE
    float*    sEs  = sEe + MAXE;                       // MAXE
    float*    sT   = sEs + MAXE;                       // 64*LDT (tf32 bits)
    unsigned* sM   = (unsigned*)(sT + K2_TILE * LDT);  // 128*LDM tf32 bits

    int tid = threadIdx.x;

    // ---- stage weights & biases ONCE per block ----
    if (tid < 128) {
        sUWB[tid] = make_float4(W1[tid], W1[HIDDEN + tid], b1[tid], 0.f);
        sc1[tid]  = c1v[tid];
        sV2[tid]  = V2[tid];
        sbb[tid]  = g_bb[tid];
    }
    for (int i = tid; i < HIDDEN * HIDDEN; i += 256) {
        int rw = i >> 7, cl = i & 127;
        sM[rw * LDM + cl] = g_Mtf[i];
    }
    float c2s = c2[0];

    int row = tid >> 2, q = tid & 3;                   // layer-1 mapping
    int w = tid >> 5, lane = tid & 31, gid = lane >> 2, tig = lane & 3;
    int wr = w & 3;                                    // row-group for mma
    int nt0 = (w >> 2) * 8;                            // nt half for mma

    for (int tile = blockIdx.x; tile < K2_NTILES; tile += K2_GRID) {
        int r_first = tile * K2_TILE;
        int e_begin = g_start[r_first];
        int last    = r_first + K2_TILE - 1;
        int totE    = g_start[last] + g_cnt[last] - e_begin;

        int r     = r_first + row;
        int s_rel = g_start[r] - e_begin;
        int c     = g_cnt[r];

        float acc[32];
        #pragma unroll
        for (int i = 0; i < 32; i++) acc[i] = 0.f;
        float exts = 0.f;

        for (int base = 0; base < totE; base += MAXE) {
            int ch = min(MAXE, totE - base);
            __syncthreads();   // sE/sT reuse boundary (covers weight staging & prev tile)
            for (int i = tid; i < ch; i += 256) {
                int idx = g_eidx[e_begin + base + i];
                int met = met_sub[idx];
                sEa[i] = x[met * 8 + 3];
                sEe[i] = x[met * 8 + 4];
                sEs[i] = sto_sub[idx];
            }
            __syncthreads();
            int lo = max(s_rel, base), hi = min(s_rel + c, base + ch);
            for (int l = lo; l < hi; l++) {
                float a   = sEa[l - base];
                float sto = sEs[l - base];
                if (q == 0) exts += sEe[l - base];
                #pragma unroll
                for (int i = 0; i < 32; i++) {
                    float4 uwb = sUWB[q + 4 * i];   // stride-4: conflict-free
                    acc[i] += tanh_fast(fmaf(a, uwb.x, fmaf(sto, uwb.y, uwb.z)));
                }
            }
        }

        #pragma unroll
        for (int i = 0; i < 32; i++)
            sT[row * LDT + q + 4 * i] = __uint_as_float(cvt_tf32(acc[i]));
        if (q == 0) { scnt[row] = (float)c; sext[row] = exts; }
        __syncthreads();

        // ---- mma phase: 8 warps; warp w handles rows of (w&3), nt half (w>>2) ----
        unsigned afr[16][4];
        #pragma unroll
        for (int kt = 0; kt < 16; kt++) {
            int k = kt * 8;
            afr[kt][0] = __float_as_uint(sT[(wr * 16 + gid)     * LDT + k + tig]);
            afr[kt][1] = __float_as_uint(sT[(wr * 16 + gid + 8) * LDT + k + tig]);
            afr[kt][2] = __float_as_uint(sT[(wr * 16 + gid)     * LDT + k + 4 + tig]);
            afr[kt][3] = __float_as_uint(sT[(wr * 16 + gid + 8) * LDT + k + 4 + tig]);
        }
        float cnt0 = scnt[wr * 16 + gid], cnt1 = scnt[wr * 16 + gid + 8];
        float acc0 = 0.f, acc1 = 0.f;

        for (int nt = nt0; nt < nt0 + 8; nt++) {
            // two accumulator sets: break the dependent-HMMA chain (depth 16 -> 8)
            float a0 = 0.f, a1 = 0.f, a2 = 0.f, a3 = 0.f;
            float d0 = 0.f, d1 = 0.f, d2 = 0.f, d3 = 0.f;
            int n0 = nt * 8;
            #pragma unroll
            for (int kt = 0; kt < 16; kt += 2) {
                unsigned b0  = sM[(kt * 8 + tig)     * LDM + n0 + gid];
                unsigned b1r = sM[(kt * 8 + tig + 4) * LDM + n0 + gid];
                asm volatile(
                    "mma.sync.aligned.m16n8k8.row.col.f32.tf32.tf32.f32 "
                    "{%0,%1,%2,%3}, {%4,%5,%6,%7}, {%8,%9}, {%0,%1,%2,%3};"
                    : "+f"(a0), "+f"(a1), "+f"(a2), "+f"(a3)
                    : "r"(afr[kt][0]), "r"(afr[kt][1]), "r"(afr[kt][2]), "r"(afr[kt][3]),
                      "r"(b0), "r"(b1r));
                unsigned c0b = sM[((kt + 1) * 8 + tig)     * LDM + n0 + gid];
                unsigned c1b = sM[((kt + 1) * 8 + tig + 4) * LDM + n0 + gid];
                asm volatile(
                    "mma.sync.aligned.m16n8k8.row.col.f32.tf32.tf32.f32 "
                    "{%0,%1,%2,%3}, {%4,%5,%6,%7}, {%8,%9}, {%0,%1,%2,%3};"
                    : "+f"(d0), "+f"(d1), "+f"(d2), "+f"(d3)
                    : "r"(afr[kt+1][0]), "r"(afr[kt+1][1]), "r"(afr[kt+1][2]), "r"(afr[kt+1][3]),
                      "r"(c0b), "r"(c1b));
            }
            float c0 = a0 + d0, c1f = a1 + d1, c2f = a2 + d2, c3f = a3 + d3;
            int col0 = n0 + 2 * tig, col1 = col0 + 1;
            float bi0 = sc1[col0], bi1 = sc1[col1];
            float bb0 = sbb[col0], bb1 = sbb[col1];
            float v0  = sV2[col0], v1  = sV2[col1];
            acc0 += tanh_fast(fmaf(cnt0, bb0, c0)  + bi0) * v0
                  + tanh_fast(fmaf(cnt0, bb1, c1f) + bi1) * v1;
            acc1 += tanh_fast(fmaf(cnt1, bb0, c2f) + bi0) * v0
                  + tanh_fast(fmaf(cnt1, bb1, c3f) + bi1) * v1;
        }

        acc0 += __shfl_xor_sync(0xffffffffu, acc0, 1);
        acc0 += __shfl_xor_sync(0xffffffffu, acc0, 2);
        acc1 += __shfl_xor_sync(0xffffffffu, acc1, 1);
        acc1 += __shfl_xor_sync(0xffffffffu, acc1, 2);

        // warps 4-7 deposit partials (rows wr*16+gid and +8 are disjoint sets)
        if (w >= 4 && tig == 0) {
            sP[wr * 16 + gid]     = acc0;
            sP[wr * 16 + gid + 8] = acc1;
        }
        __syncthreads();

        if (w < 4 && tig == 0) {
            acc0 += sP[wr * 16 + gid];
            acc1 += sP[wr * 16 + gid + 8];
            int r0 = r_first + wr * 16 + gid;
            {
                float z    = acc0 + c2s;
                float base = fmaxf(z, 0.f) + log1pf(expf(-fabsf(z)));
                float extm = sext[wr * 16 + gid] / fmaxf(scnt[wr * 16 + gid], 1.f);
                g_v[r0]      = exp10f(log_k[r0]) * extm * base;
                g_rscale[r0] = 1.f;
            }
            int r1 = r0 + 8;
            {
                float z    = acc1 + c2s;
                float base = fmaxf(z, 0.f) + log1pf(expf(-fabsf(z)));
                float extm = sext[wr * 16 + gid + 8] / fmaxf(scnt[wr * 16 + gid + 8], 1.f);
                g_v[r1]      = exp10f(log_k[r1]) * extm * base;
                g_rscale[r1] = 1.f;
            }
        }
    }
}

// ---------------- small scatter kernels ---------------------------------------
__global__ void k_totcons(const int* __restrict__ met_sub,
                          const int* __restrict__ rxn_sub,
                          const float* __restrict__ sto_sub)
{
    int e = blockIdx.x * blockDim.x + threadIdx.x;
    if (e >= E_SUB) return;
    float c = sto_sub[e] * g_v[rxn_sub[e]] * DT;
    atomicAdd(&g_totcons[met_sub[e]], c);
}

__global__ void k_rscale(const float* __restrict__ x,
                         const int* __restrict__ met_sub,
                         const int* __restrict__ rxn_sub)
{
    int e = blockIdx.x * blockDim.x + threadIdx.x;
    if (e >= E_SUB) return;
    int   m    = met_sub[e];
    float tot  = g_totcons[m];
    float conc = x[m * 8 + 3];
    float sc   = (tot > 1e-12f) ? fminf(conc / tot, 1.0f) : 1.0f;
    atomicMin(reinterpret_cast<int*>(&g_rscale[rxn_sub[e]]), __float_as_int(sc));
}

__global__ void k_contrib(const int* __restrict__ met_sub,
                          const int* __restrict__ rxn_sub,
                          const float* __restrict__ sto_sub,
                          const int* __restrict__ met_prod,
                          const int* __restrict__ rxn_prod,
                          const float* __restrict__ sto_prod,
                          float* __restrict__ out)
{
    int i = blockIdx.x * blockDim.x + threadIdx.x;
    if (i >= E_SUB + E_PROD) return;
    int m, r; float sto;
    if (i < E_SUB) {
        m = met_sub[i];  r = rxn_sub[i];  sto = -sto_sub[i];
    } else {
        int e = i - E_SUB;
        m = met_prod[e]; r = rxn_prod[e]; sto = sto_prod[e];
    }
    atomicAdd(&out[m], sto * g_v[r] * g_rscale[r]);
}

// ---------------- launch ------------------------------------------------------
extern "C" void kernel_launch(void* const* d_in, const int* in_sizes, int n_in,
                              void* d_out, int out_size)
{
    const float* x        = (const float*)d_in[0];
    const int*   met_sub  = (const int*)  d_in[1];
    const int*   rxn_sub  = (const int*)  d_in[2];
    const float* sto_sub  = (const float*)d_in[3];
    const int*   met_prod = (const int*)  d_in[4];
    const int*   rxn_prod = (const int*)  d_in[5];
    const float* sto_prod = (const float*)d_in[6];
    const float* W1       = (const float*)d_in[7];
    const float* b1       = (const float*)d_in[8];
    const float* W2       = (const float*)d_in[9];
    const float* b2       = (const float*)d_in[10];
    const float* V1       = (const float*)d_in[11];
    const float* c1       = (const float*)d_in[12];
    const float* V2       = (const float*)d_in[13];
    const float* c2       = (const float*)d_in[14];
    const float* log_k    = (const float*)d_in[15];
    float* out = (float*)d_out;

    cudaFuncSetAttribute(k2_gemm, cudaFuncAttributeMaxDynamicSharedMemorySize,
                         K2_SMEM_BYTES);

    k_init<<<129 + 1024, 128>>>(W2, V1, b2, out);

    k_hist<<<(E_SUB + 255) / 256, 256>>>(rxn_sub);
    k_scan1<<<NB1, SCAN_BS>>>();
    k_scan2<<<1, SCAN_BS>>>();
    k_start<<<(N_RXN + 255) / 256, 256>>>();
    k_scatter<<<(E_SUB + 255) / 256, 256>>>(rxn_sub);

    k2_gemm<<<K2_GRID, 256, K2_SMEM_BYTES>>>(x, met_sub, sto_sub,
                                             W1, b1, c1, V2, c2, log_k);

    k_totcons<<<(E_SUB + 255) / 256, 256>>>(met_sub, rxn_sub, sto_sub);
    k_rscale<<<(E_SUB + 255) / 256, 256>>>(x, met_sub, rxn_sub);
    k_contrib<<<(E_SUB + E_PROD + 255) / 256, 256>>>(
        met_sub, rxn_sub, sto_sub, met_prod, rxn_prod, sto_prod, out);
}